// round 6
// baseline (speedup 1.0000x reference)
#include <cuda_runtime.h>
#include <cuda_bf16.h>
#include <math.h>
#include <stdint.h>

// Fixed problem shape: n=8192, k=128, h=128
#define N_FIX 8192
#define KDIM 128
#define BM 64
#define BK 32
#define NITER (N_FIX / BK)   // 256
// dynamic smem: B stages [0,32768) 4 x 8KB ; A bufs [32768, 43008) 2 x 5120B
#define ABASE 32768
#define ABUF 5120
#define SMEM_BYTES (32768 + 2 * ABUF)

// ---------------- device scratch ----------------
__device__ __align__(16) __nv_bfloat16 g_Cb[(size_t)N_FIX * KDIM];
__device__ float g_col[KDIM];
__device__ float g_diag[KDIM];
__device__ float g_sA;
__device__ float g_hpart;
__device__ int g_cnt;

// ---------------- helpers ----------------
__device__ __forceinline__ uint32_t smem_u32(const void* p) {
    uint32_t a;
    asm("{ .reg .u64 t; cvta.to.shared.u64 t, %1; cvt.u32.u64 %0, t; }" : "=r"(a) : "l"(p));
    return a;
}
__device__ __forceinline__ void cp16(uint32_t saddr, const void* gp) {
    unsigned long long g = __cvta_generic_to_global(gp);
    asm volatile("cp.async.cg.shared.global [%0], [%1], 16;" :: "r"(saddr), "l"(g) : "memory");
}
#define CP_COMMIT() asm volatile("cp.async.commit_group;" ::: "memory")
#define CP_WAIT2()  asm volatile("cp.async.wait_group 2;" ::: "memory")

__device__ __forceinline__ uint32_t cvt_bf2(float x, float y) {
    uint32_t r;  // low = x, high = y
    asm("cvt.rn.bf16x2.f32 %0, %1, %2;" : "=r"(r) : "f"(y), "f"(x));
    return r;
}
__device__ __forceinline__ void ldmx4(uint32_t* r, uint32_t addr) {
    asm volatile("ldmatrix.sync.aligned.m8n8.x4.shared.b16 {%0,%1,%2,%3}, [%4];"
                 : "=r"(r[0]), "=r"(r[1]), "=r"(r[2]), "=r"(r[3]) : "r"(addr));
}
__device__ __forceinline__ void ldmx4t(uint32_t& r0, uint32_t& r1, uint32_t& r2,
                                       uint32_t& r3, uint32_t addr) {
    asm volatile("ldmatrix.sync.aligned.m8n8.x4.trans.shared.b16 {%0,%1,%2,%3}, [%4];"
                 : "=r"(r0), "=r"(r1), "=r"(r2), "=r"(r3) : "r"(addr));
}
__device__ __forceinline__ void mma16816(float* d, const uint32_t* a, uint32_t b0,
                                         uint32_t b1) {
    asm volatile(
        "mma.sync.aligned.m16n8k16.row.col.f32.bf16.bf16.f32 "
        "{%0,%1,%2,%3}, {%4,%5,%6,%7}, {%8,%9}, {%0,%1,%2,%3};"
        : "+f"(d[0]), "+f"(d[1]), "+f"(d[2]), "+f"(d[3])
        : "r"(a[0]), "r"(a[1]), "r"(a[2]), "r"(a[3]), "r"(b0), "r"(b1));
}

// ---------------- C -> bf16 + global init ----------------
__global__ void __launch_bounds__(256) k_prep(const float* __restrict__ C) {
    if (blockIdx.x == 0) {
        int t = threadIdx.x;
        if (t < KDIM) { g_col[t] = 0.0f; g_diag[t] = 0.0f; }
        if (t == 0) { g_sA = 0.0f; g_hpart = 0.0f; g_cnt = 0; }
    }
    size_t base = ((size_t)blockIdx.x * 256 + threadIdx.x) * 16;
    const float4* src = reinterpret_cast<const float4*>(C + base);
    uint32_t o[8];
#pragma unroll
    for (int q = 0; q < 4; ++q) {
        float4 v = __ldg(&src[q]);
        o[q * 2 + 0] = cvt_bf2(v.x, v.y);
        o[q * 2 + 1] = cvt_bf2(v.z, v.w);
    }
    uint4* dst = reinterpret_cast<uint4*>(g_Cb + base);
    dst[0] = make_uint4(o[0], o[1], o[2], o[3]);
    dst[1] = make_uint4(o[4], o[5], o[6], o[7]);
}

// ---------------- fully fused GEMM + all reductions + final ----------------
__global__ void __launch_bounds__(256) k_gemm(const float* __restrict__ A,
                                              const float* __restrict__ C,
                                              const float* __restrict__ H,
                                              const float* __restrict__ papra,
                                              const int* __restrict__ flag,
                                              float* __restrict__ out, int out_size) {
    extern __shared__ __align__(1024) char smem[];
    __shared__ float scol[KDIM], sdiag[KDIM], srow[BM], sr1[BM], sr2[BM], swarp[4];
    __shared__ int is_last;

    const int tid = threadIdx.x, lane = tid & 31, wid = tid >> 5;
    const int wm = wid & 1, wn = wid >> 1;   // 2 M-warps x 4 N-warps
    const int blockRow = blockIdx.x * BM;
    const uint32_t su = smem_u32(smem);

    if (tid < KDIM) { scol[tid] = 0.0f; sdiag[tid] = 0.0f; }

    // ---- A load mapping: 64 rows x 32 fp32 per iter; 4 threads/row, 8 floats each
    const int arow = tid >> 2;
    const int acg = (tid & 3) * 8;
    const float* gA = A + (size_t)(blockRow + arow) * N_FIX + acg;
    char* aST = smem + ABASE + arow * 80 + (tid & 3) * 16;

    // ---- B cp.async mapping: 8KB/iter = 512 chunks, 2 per thread
    const int ch0 = tid, ch1 = tid + 256;
    const int kB0 = ch0 >> 4, cB0 = ch0 & 15;
    const int kB1 = ch1 >> 4, cB1 = ch1 & 15;
    const uint32_t sB0 = (uint32_t)(kB0 * 256 + ((cB0 ^ (kB0 & 7)) << 4));
    const uint32_t sB1 = (uint32_t)(kB1 * 256 + ((cB1 ^ (kB1 & 7)) << 4));
    const __nv_bfloat16* gB0 = g_Cb + kB0 * KDIM + cB0 * 8;
    const __nv_bfloat16* gB1 = g_Cb + kB1 * KDIM + cB1 * 8;

    // ---- LDSM A offsets [mt][kq] (80B row stride; 5 coprime 8 -> conflict-free)
    uint32_t aoff[2][2];
    {
        int r = wm * 32 + (lane & 7) + ((lane >> 3) & 1) * 8;
        int ckl = lane >> 4;  // 0/1 k-half within k16
#pragma unroll
        for (int mt = 0; mt < 2; ++mt)
#pragma unroll
            for (int kq = 0; kq < 2; ++kq)
                aoff[mt][kq] = su + ABASE + (uint32_t)((r + mt * 16) * 80 + (kq * 2 + ckl) * 16);
    }
    // ---- LDSM B (trans) offsets [g][kq]
    uint32_t boff[2][2];
    {
        int mM = lane >> 3, iR = lane & 7;
        int kkb = (mM & 1) * 8 + iR;
#pragma unroll
        for (int g = 0; g < 2; ++g)
#pragma unroll
            for (int kq = 0; kq < 2; ++kq) {
                int k = kq * 16 + kkb;
                int nn = wn * 32 + g * 16 + (mM >> 1) * 8;
                uint32_t off = (uint32_t)(k * 256 + nn * 2);
                boff[g][kq] = su + (off ^ ((k & 7) << 4));
            }
    }

    float acc[2][4][4];
#pragma unroll
    for (int mt = 0; mt < 2; ++mt)
#pragma unroll
        for (int nt = 0; nt < 4; ++nt)
#pragma unroll
            for (int e = 0; e < 4; ++e) acc[mt][nt][e] = 0.0f;
    float dsum = 0.0f;

    // ---- prologue: A(0) via regs, B stages 0..2 via cp.async
    {
        float4 a0 = __ldg(reinterpret_cast<const float4*>(gA));
        float4 a1 = __ldg(reinterpret_cast<const float4*>(gA) + 1);
        dsum += (a0.x + a0.y) + (a0.z + a0.w) + (a1.x + a1.y) + (a1.z + a1.w);
        uint4 st = make_uint4(cvt_bf2(a0.x, a0.y), cvt_bf2(a0.z, a0.w),
                              cvt_bf2(a1.x, a1.y), cvt_bf2(a1.z, a1.w));
        *reinterpret_cast<uint4*>(aST) = st;
    }
#pragma unroll
    for (int s = 0; s < 3; ++s) {
        cp16(su + s * 8192 + sB0, gB0 + (size_t)s * 4096);
        cp16(su + s * 8192 + sB1, gB1 + (size_t)s * 4096);
        CP_COMMIT();
    }

    // ---- main loop ----
    for (int it = 0; it < NITER; ++it) {
        CP_WAIT2();
        __syncthreads();
        const uint32_t abuf = (uint32_t)((it & 1) * ABUF);
        const uint32_t sst = (uint32_t)((it & 3) * 8192);
        const int nit = it + 1;

        float4 na0, na1;
        if (nit < NITER) {
            na0 = __ldg(reinterpret_cast<const float4*>(gA + (size_t)nit * BK));
            na1 = __ldg(reinterpret_cast<const float4*>(gA + (size_t)nit * BK) + 1);
        }
        const int pit = it + 3;
        if (pit < NITER) {
            uint32_t sb = su + (pit & 3) * 8192;
            cp16(sb + sB0, gB0 + (size_t)pit * 4096);
            cp16(sb + sB1, gB1 + (size_t)pit * 4096);
        }
        CP_COMMIT();

#pragma unroll
        for (int kq = 0; kq < 2; ++kq) {
            uint32_t ra0[4], ra1[4];
            ldmx4(ra0, aoff[0][kq] + abuf);
            ldmx4(ra1, aoff[1][kq] + abuf);
#pragma unroll
            for (int g = 0; g < 2; ++g) {
                uint32_t b0, b1, b2, b3;
                ldmx4t(b0, b1, b2, b3, boff[g][kq] + sst);
                mma16816(acc[0][2 * g], ra0, b0, b1);
                mma16816(acc[0][2 * g + 1], ra0, b2, b3);
                mma16816(acc[1][2 * g], ra1, b0, b1);
                mma16816(acc[1][2 * g + 1], ra1, b2, b3);
            }
        }

        if (nit < NITER) {
            dsum += (na0.x + na0.y) + (na0.z + na0.w) + (na1.x + na1.y) + (na1.z + na1.w);
            uint4 st = make_uint4(cvt_bf2(na0.x, na0.y), cvt_bf2(na0.z, na0.w),
                                  cvt_bf2(na1.x, na1.y), cvt_bf2(na1.z, na1.w));
            *reinterpret_cast<uint4*>(aST + (nit & 1) * ABUF) = st;
        }
    }

    // ---- row sums (exact fp32) into smem ----
    dsum += __shfl_xor_sync(0xffffffffu, dsum, 1);
    dsum += __shfl_xor_sync(0xffffffffu, dsum, 2);
    if ((tid & 3) == 0) srow[arow] = dsum;

    // ---- colsum(M) and diag = sum_i C[i][j]*M[i][j] ----
#pragma unroll
    for (int nt = 0; nt < 4; ++nt) {
        const int col = wn * 32 + nt * 8 + (lane & 3) * 2;
        const int r0 = blockRow + wm * 32 + (lane >> 2);
        float2 c00 = *reinterpret_cast<const float2*>(C + (size_t)r0 * KDIM + col);
        float2 c08 = *reinterpret_cast<const float2*>(C + (size_t)(r0 + 8) * KDIM + col);
        float2 c16 = *reinterpret_cast<const float2*>(C + (size_t)(r0 + 16) * KDIM + col);
        float2 c24 = *reinterpret_cast<const float2*>(C + (size_t)(r0 + 24) * KDIM + col);
        float cs0 = acc[0][nt][0] + acc[0][nt][2] + acc[1][nt][0] + acc[1][nt][2];
        float cs1 = acc[0][nt][1] + acc[0][nt][3] + acc[1][nt][1] + acc[1][nt][3];
        float ds0 = c00.x * acc[0][nt][0] + c08.x * acc[0][nt][2] +
                    c16.x * acc[1][nt][0] + c24.x * acc[1][nt][2];
        float ds1 = c00.y * acc[0][nt][1] + c08.y * acc[0][nt][3] +
                    c16.y * acc[1][nt][1] + c24.y * acc[1][nt][3];
#pragma unroll
        for (int o = 4; o <= 16; o <<= 1) {
            cs0 += __shfl_xor_sync(0xffffffffu, cs0, o);
            cs1 += __shfl_xor_sync(0xffffffffu, cs1, o);
            ds0 += __shfl_xor_sync(0xffffffffu, ds0, o);
            ds1 += __shfl_xor_sync(0xffffffffu, ds1, o);
        }
        if (lane < 4) {
            const int cc = wn * 32 + nt * 8 + lane * 2;
            atomicAdd(&scol[cc], cs0);
            atomicAdd(&scol[cc + 1], cs1);
            atomicAdd(&sdiag[cc], ds0);
            atomicAdd(&sdiag[cc + 1], ds1);
        }
    }
    __syncthreads();
    if (tid < KDIM) {
        atomicAdd(&g_col[tid], scol[tid]);
        atomicAdd(&g_diag[tid], sdiag[tid]);
    }

    // ---- h_part + sA for this CTA's 64 rows ----
    {
        const float4* hp = reinterpret_cast<const float4*>(
            H + (size_t)(blockRow + arow) * KDIM + (tid & 3) * 32);
        float h2 = 0.0f;
#pragma unroll
        for (int q = 0; q < 8; ++q) {
            float4 v = __ldg(&hp[q]);
            h2 += v.x * v.x + v.y * v.y + v.z * v.z + v.w * v.w;
        }
        h2 += __shfl_xor_sync(0xffffffffu, h2, 1);
        h2 += __shfl_xor_sync(0xffffffffu, h2, 2);
        if ((tid & 3) == 0) {
            float d = srow[arow];
            sr1[arow] = d * h2;
            sr2[arow] = d;
        }
        __syncthreads();
        if (tid < 32) {
            float a1 = sr1[tid] + sr1[tid + 32];
            float a2 = sr2[tid] + sr2[tid + 32];
#pragma unroll
            for (int o = 16; o > 0; o >>= 1) {
                a1 += __shfl_xor_sync(0xffffffffu, a1, o);
                a2 += __shfl_xor_sync(0xffffffffu, a2, o);
            }
            if (tid == 0) {
                atomicAdd(&g_hpart, a1);
                atomicAdd(&g_sA, a2);
            }
        }
    }

    // ---- last CTA computes final scalars ----
    if (tid == 0) {
        __threadfence();
        int c = atomicAdd(&g_cnt, 1);
        is_last = (c == (int)gridDim.x - 1);
    }
    __syncthreads();
    if (is_last) {
        float t = 0.0f;
        float sA = *(volatile float*)&g_sA;
        if (tid < KDIM) {
            float dg = *(volatile float*)&g_diag[tid];
            float cl = *(volatile float*)&g_col[tid];
            t = dg * log2f(cl / sA + 1e-40f);
        }
#pragma unroll
        for (int o = 16; o > 0; o >>= 1) t += __shfl_xor_sync(0xffffffffu, t, o);
        if (lane == 0 && wid < 4) swarp[wid] = t;
        __syncthreads();
        if (tid == 0) {
            float total = (swarp[0] + swarp[1] + swarp[2] + swarp[3]) / sA;
            float hp = *(volatile float*)&g_hpart;
            int fl = flag ? *flag : 20;
            float pw = papra ? *papra : 1.0f;
            if (fl > 10) total += pw * hp;
            out[0] = total;
            if (out_size > 1) out[1] = hp;
        }
    }
}

extern "C" void kernel_launch(void* const* d_in, const int* in_sizes, int n_in,
                              void* d_out, int out_size) {
    const float* A = (const float*)d_in[0];
    const float* C = (const float*)d_in[1];
    const float* H = (const float*)d_in[2];
    const float* papra = (n_in > 3) ? (const float*)d_in[3] : nullptr;
    const int* flag = (n_in > 4) ? (const int*)d_in[4] : nullptr;

    cudaFuncSetAttribute(k_gemm, cudaFuncAttributeMaxDynamicSharedMemorySize, SMEM_BYTES);

    k_prep<<<(N_FIX * KDIM) / (256 * 16), 256>>>(C);
    k_gemm<<<N_FIX / BM, 256, SMEM_BYTES>>>(A, C, H, papra, flag, (float*)d_out, out_size);
}

// round 7
// speedup vs baseline: 1.5118x; 1.5118x over previous
#include <cuda_runtime.h>
#include <cuda_bf16.h>
#include <math.h>
#include <stdint.h>

// Fixed problem shape: n=8192, k=128, h=128
#define N_FIX 8192
#define KDIM 128
#define BM 64
#define BK 32
#define NITER (N_FIX / BK)   // 256
// dynamic smem: B stages [0,32768) 4 x 8KB ; A bufs [32768, +2*5120)
#define ABASE 32768
#define ABUF 5120
#define SMEM_BYTES (32768 + 2 * ABUF)

// ---------------- device scratch ----------------
__device__ __align__(16) __nv_bfloat16 g_Cb[(size_t)N_FIX * KDIM];
__device__ float g_col[KDIM];
__device__ float g_diag[KDIM];
__device__ float g_sA;
__device__ float g_hpart;
__device__ int g_cnt;

// ---------------- helpers ----------------
__device__ __forceinline__ uint32_t smem_u32(const void* p) {
    uint32_t a;
    asm("{ .reg .u64 t; cvta.to.shared.u64 t, %1; cvt.u32.u64 %0, t; }" : "=r"(a) : "l"(p));
    return a;
}
__device__ __forceinline__ void cp16(uint32_t saddr, const void* gp) {
    unsigned long long g = __cvta_generic_to_global(gp);
    asm volatile("cp.async.cg.shared.global [%0], [%1], 16;" :: "r"(saddr), "l"(g) : "memory");
}
#define CP_COMMIT() asm volatile("cp.async.commit_group;" ::: "memory")
#define CP_WAIT2()  asm volatile("cp.async.wait_group 2;" ::: "memory")

__device__ __forceinline__ uint32_t cvt_bf2(float x, float y) {
    uint32_t r;  // low = x, high = y
    asm("cvt.rn.bf16x2.f32 %0, %1, %2;" : "=r"(r) : "f"(y), "f"(x));
    return r;
}
__device__ __forceinline__ void ldmx4(uint32_t* r, uint32_t addr) {
    asm volatile("ldmatrix.sync.aligned.m8n8.x4.shared.b16 {%0,%1,%2,%3}, [%4];"
                 : "=r"(r[0]), "=r"(r[1]), "=r"(r[2]), "=r"(r[3]) : "r"(addr));
}
__device__ __forceinline__ void ldmx4t(uint32_t& r0, uint32_t& r1, uint32_t& r2,
                                       uint32_t& r3, uint32_t addr) {
    asm volatile("ldmatrix.sync.aligned.m8n8.x4.trans.shared.b16 {%0,%1,%2,%3}, [%4];"
                 : "=r"(r0), "=r"(r1), "=r"(r2), "=r"(r3) : "r"(addr));
}
__device__ __forceinline__ void mma16816(float* d, const uint32_t* a, uint32_t b0,
                                         uint32_t b1) {
    asm volatile(
        "mma.sync.aligned.m16n8k16.row.col.f32.bf16.bf16.f32 "
        "{%0,%1,%2,%3}, {%4,%5,%6,%7}, {%8,%9}, {%0,%1,%2,%3};"
        : "+f"(d[0]), "+f"(d[1]), "+f"(d[2]), "+f"(d[3])
        : "r"(a[0]), "r"(a[1]), "r"(a[2]), "r"(a[3]), "r"(b0), "r"(b1));
}

// ---------------- C -> bf16 + global init ----------------
__global__ void __launch_bounds__(256) k_prep(const float* __restrict__ C) {
    if (blockIdx.x == 0) {
        int t = threadIdx.x;
        if (t < KDIM) { g_col[t] = 0.0f; g_diag[t] = 0.0f; }
        if (t == 0) { g_sA = 0.0f; g_hpart = 0.0f; g_cnt = 0; }
    }
    size_t base = ((size_t)blockIdx.x * 256 + threadIdx.x) * 16;
    const float4* src = reinterpret_cast<const float4*>(C + base);
    uint32_t o[8];
#pragma unroll
    for (int q = 0; q < 4; ++q) {
        float4 v = __ldg(&src[q]);
        o[q * 2 + 0] = cvt_bf2(v.x, v.y);
        o[q * 2 + 1] = cvt_bf2(v.z, v.w);
    }
    uint4* dst = reinterpret_cast<uint4*>(g_Cb + base);
    dst[0] = make_uint4(o[0], o[1], o[2], o[3]);
    dst[1] = make_uint4(o[4], o[5], o[6], o[7]);
}

// ---------------- fully fused GEMM + all reductions + final ----------------
__global__ void __launch_bounds__(256) k_gemm(const float* __restrict__ A,
                                              const float* __restrict__ C,
                                              const float* __restrict__ H,
                                              const float* __restrict__ papra,
                                              const int* __restrict__ flag,
                                              float* __restrict__ out, int out_size) {
    extern __shared__ __align__(1024) char smem[];
    __shared__ float scol[KDIM], sdiag[KDIM], srow[BM], sr1[BM], sr2[BM], swarp[4];
    __shared__ int is_last;

    const int tid = threadIdx.x, lane = tid & 31, wid = tid >> 5;
    const int wm = wid & 1, wn = wid >> 1;   // 2 M-warps x 4 N-warps
    const int blockRow = blockIdx.x * BM;
    const uint32_t su = smem_u32(smem);

    if (tid < KDIM) { scol[tid] = 0.0f; sdiag[tid] = 0.0f; }

    // ---- A load mapping: 64 rows x 32 fp32 per tile; 4 threads/row, 8 floats each
    const int arow = tid >> 2;
    const float* gA = A + (size_t)(blockRow + arow) * N_FIX + (tid & 3) * 8;
    char* aST = smem + ABASE + arow * 80 + (tid & 3) * 16;

    // ---- B cp.async mapping: 8KB/tile = 512 chunks, 2 per thread
    const int ch0 = tid, ch1 = tid + 256;
    const int kB0 = ch0 >> 4, cB0 = ch0 & 15;
    const int kB1 = ch1 >> 4, cB1 = ch1 & 15;
    const uint32_t sB0 = (uint32_t)(kB0 * 256 + ((cB0 ^ (kB0 & 7)) << 4));
    const uint32_t sB1 = (uint32_t)(kB1 * 256 + ((cB1 ^ (kB1 & 7)) << 4));
    const __nv_bfloat16* gB0 = g_Cb + kB0 * KDIM + cB0 * 8;
    const __nv_bfloat16* gB1 = g_Cb + kB1 * KDIM + cB1 * 8;

    // ---- LDSM A offsets [mt][kq] (80B row stride; 5 coprime 8 -> conflict-free)
    uint32_t aoff[2][2];
    {
        int r = wm * 32 + (lane & 7) + ((lane >> 3) & 1) * 8;
        int ckl = lane >> 4;  // 0/1 k-half within k16
#pragma unroll
        for (int mt = 0; mt < 2; ++mt)
#pragma unroll
            for (int kq = 0; kq < 2; ++kq)
                aoff[mt][kq] = su + ABASE + (uint32_t)((r + mt * 16) * 80 + (kq * 2 + ckl) * 16);
    }
    // ---- LDSM B (trans) offsets [g][kq]
    uint32_t boff[2][2];
    {
        int mM = lane >> 3, iR = lane & 7;
        int kkb = (mM & 1) * 8 + iR;
#pragma unroll
        for (int g = 0; g < 2; ++g)
#pragma unroll
            for (int kq = 0; kq < 2; ++kq) {
                int k = kq * 16 + kkb;
                int nn = wn * 32 + g * 16 + (mM >> 1) * 8;
                uint32_t off = (uint32_t)(k * 256 + nn * 2);
                boff[g][kq] = su + (off ^ ((k & 7) << 4));
            }
    }

    float acc[2][4][4];
#pragma unroll
    for (int mt = 0; mt < 2; ++mt)
#pragma unroll
        for (int nt = 0; nt < 4; ++nt)
#pragma unroll
            for (int e = 0; e < 4; ++e) acc[mt][nt][e] = 0.0f;
    float dsum = 0.0f;

    // ---- A register pipeline, depth 4: ab[t%4] holds tile t ----
    float4 ab0[4], ab1[4];
#pragma unroll
    for (int s = 0; s < 4; ++s) {
        ab0[s] = __ldg(reinterpret_cast<const float4*>(gA + (size_t)s * BK));
        ab1[s] = __ldg(reinterpret_cast<const float4*>(gA + (size_t)s * BK) + 1);
    }
    // STS tile 0
    {
        dsum += (ab0[0].x + ab0[0].y) + (ab0[0].z + ab0[0].w) +
                (ab1[0].x + ab1[0].y) + (ab1[0].z + ab1[0].w);
        uint4 st = make_uint4(cvt_bf2(ab0[0].x, ab0[0].y), cvt_bf2(ab0[0].z, ab0[0].w),
                              cvt_bf2(ab1[0].x, ab1[0].y), cvt_bf2(ab1[0].z, ab1[0].w));
        *reinterpret_cast<uint4*>(aST) = st;
    }
    // B stages 0..2
#pragma unroll
    for (int s = 0; s < 3; ++s) {
        cp16(su + s * 8192 + sB0, gB0 + (size_t)s * 4096);
        cp16(su + s * 8192 + sB1, gB1 + (size_t)s * 4096);
        CP_COMMIT();
    }

    // ---- main loop (unroll 4 so all rotating indices constant-fold) ----
#pragma unroll 4
    for (int it = 0; it < NITER; ++it) {
        CP_WAIT2();
        __syncthreads();
        const uint32_t abuf = (uint32_t)((it & 1) * ABUF);
        const uint32_t sst = (uint32_t)((it & 3) * 8192);

        // refill A register slot with tile it+4
        const int fit = it + 4;
        if (fit < NITER) {
            ab0[it & 3] = __ldg(reinterpret_cast<const float4*>(gA + (size_t)fit * BK));
            ab1[it & 3] = __ldg(reinterpret_cast<const float4*>(gA + (size_t)fit * BK) + 1);
        }
        // B prefetch stage it+3
        const int pit = it + 3;
        if (pit < NITER) {
            uint32_t sb = su + (pit & 3) * 8192;
            cp16(sb + sB0, gB0 + (size_t)pit * 4096);
            cp16(sb + sB1, gB1 + (size_t)pit * 4096);
        }
        CP_COMMIT();

#pragma unroll
        for (int kq = 0; kq < 2; ++kq) {
            uint32_t ra0[4], ra1[4];
            ldmx4(ra0, aoff[0][kq] + abuf);
            ldmx4(ra1, aoff[1][kq] + abuf);
#pragma unroll
            for (int g = 0; g < 2; ++g) {
                uint32_t b0, b1, b2, b3;
                ldmx4t(b0, b1, b2, b3, boff[g][kq] + sst);
                mma16816(acc[0][2 * g], ra0, b0, b1);
                mma16816(acc[0][2 * g + 1], ra0, b2, b3);
                mma16816(acc[1][2 * g], ra1, b0, b1);
                mma16816(acc[1][2 * g + 1], ra1, b2, b3);
            }
        }

        // STS tile it+1 (filled 3 iterations ago -> latency covered)
        const int nit = it + 1;
        if (nit < NITER) {
            const float4 na0 = ab0[nit & 3], na1 = ab1[nit & 3];
            dsum += (na0.x + na0.y) + (na0.z + na0.w) + (na1.x + na1.y) + (na1.z + na1.w);
            uint4 st = make_uint4(cvt_bf2(na0.x, na0.y), cvt_bf2(na0.z, na0.w),
                                  cvt_bf2(na1.x, na1.y), cvt_bf2(na1.z, na1.w));
            *reinterpret_cast<uint4*>(aST + (nit & 1) * ABUF) = st;
        }
    }

    // ---- row sums (exact fp32) into smem ----
    dsum += __shfl_xor_sync(0xffffffffu, dsum, 1);
    dsum += __shfl_xor_sync(0xffffffffu, dsum, 2);
    if ((tid & 3) == 0) srow[arow] = dsum;

    // ---- colsum(M) and diag = sum_i C[i][j]*M[i][j] ----
#pragma unroll
    for (int nt = 0; nt < 4; ++nt) {
        const int col = wn * 32 + nt * 8 + (lane & 3) * 2;
        const int r0 = blockRow + wm * 32 + (lane >> 2);
        float2 c00 = *reinterpret_cast<const float2*>(C + (size_t)r0 * KDIM + col);
        float2 c08 = *reinterpret_cast<const float2*>(C + (size_t)(r0 + 8) * KDIM + col);
        float2 c16 = *reinterpret_cast<const float2*>(C + (size_t)(r0 + 16) * KDIM + col);
        float2 c24 = *reinterpret_cast<const float2*>(C + (size_t)(r0 + 24) * KDIM + col);
        float cs0 = acc[0][nt][0] + acc[0][nt][2] + acc[1][nt][0] + acc[1][nt][2];
        float cs1 = acc[0][nt][1] + acc[0][nt][3] + acc[1][nt][1] + acc[1][nt][3];
        float ds0 = c00.x * acc[0][nt][0] + c08.x * acc[0][nt][2] +
                    c16.x * acc[1][nt][0] + c24.x * acc[1][nt][2];
        float ds1 = c00.y * acc[0][nt][1] + c08.y * acc[0][nt][3] +
                    c16.y * acc[1][nt][1] + c24.y * acc[1][nt][3];
#pragma unroll
        for (int o = 4; o <= 16; o <<= 1) {
            cs0 += __shfl_xor_sync(0xffffffffu, cs0, o);
            cs1 += __shfl_xor_sync(0xffffffffu, cs1, o);
            ds0 += __shfl_xor_sync(0xffffffffu, ds0, o);
            ds1 += __shfl_xor_sync(0xffffffffu, ds1, o);
        }
        if (lane < 4) {
            const int cc = wn * 32 + nt * 8 + lane * 2;
            atomicAdd(&scol[cc], cs0);
            atomicAdd(&scol[cc + 1], cs1);
            atomicAdd(&sdiag[cc], ds0);
            atomicAdd(&sdiag[cc + 1], ds1);
        }
    }
    __syncthreads();
    if (tid < KDIM) {
        atomicAdd(&g_col[tid], scol[tid]);
        atomicAdd(&g_diag[tid], sdiag[tid]);
    }

    // ---- h_part + sA for this CTA's 64 rows ----
    {
        const float4* hp = reinterpret_cast<const float4*>(
            H + (size_t)(blockRow + arow) * KDIM + (tid & 3) * 32);
        float h2 = 0.0f;
#pragma unroll
        for (int q = 0; q < 8; ++q) {
            float4 v = __ldg(&hp[q]);
            h2 += v.x * v.x + v.y * v.y + v.z * v.z + v.w * v.w;
        }
        h2 += __shfl_xor_sync(0xffffffffu, h2, 1);
        h2 += __shfl_xor_sync(0xffffffffu, h2, 2);
        if ((tid & 3) == 0) {
            float d = srow[arow];
            sr1[arow] = d * h2;
            sr2[arow] = d;
        }
        __syncthreads();
        if (tid < 32) {
            float a1 = sr1[tid] + sr1[tid + 32];
            float a2 = sr2[tid] + sr2[tid + 32];
#pragma unroll
            for (int o = 16; o > 0; o >>= 1) {
                a1 += __shfl_xor_sync(0xffffffffu, a1, o);
                a2 += __shfl_xor_sync(0xffffffffu, a2, o);
            }
            if (tid == 0) {
                atomicAdd(&g_hpart, a1);
                atomicAdd(&g_sA, a2);
            }
        }
    }

    // ---- last CTA computes final scalars ----
    if (tid == 0) {
        __threadfence();
        int c = atomicAdd(&g_cnt, 1);
        is_last = (c == (int)gridDim.x - 1);
    }
    __syncthreads();
    if (is_last) {
        float t = 0.0f;
        float sA = *(volatile float*)&g_sA;
        if (tid < KDIM) {
            float dg = *(volatile float*)&g_diag[tid];
            float cl = *(volatile float*)&g_col[tid];
            t = dg * log2f(cl / sA + 1e-40f);
        }
#pragma unroll
        for (int o = 16; o > 0; o >>= 1) t += __shfl_xor_sync(0xffffffffu, t, o);
        if (lane == 0 && wid < 4) swarp[wid] = t;
        __syncthreads();
        if (tid == 0) {
            float total = (swarp[0] + swarp[1] + swarp[2] + swarp[3]) / sA;
            float hp = *(volatile float*)&g_hpart;
            int fl = flag ? *flag : 20;
            float pw = papra ? *papra : 1.0f;
            if (fl > 10) total += pw * hp;
            out[0] = total;
            if (out_size > 1) out[1] = hp;
        }
    }
}

extern "C" void kernel_launch(void* const* d_in, const int* in_sizes, int n_in,
                              void* d_out, int out_size) {
    const float* A = (const float*)d_in[0];
    const float* C = (const float*)d_in[1];
    const float* H = (const float*)d_in[2];
    const float* papra = (n_in > 3) ? (const float*)d_in[3] : nullptr;
    const int* flag = (n_in > 4) ? (const int*)d_in[4] : nullptr;

    cudaFuncSetAttribute(k_gemm, cudaFuncAttributeMaxDynamicSharedMemorySize, SMEM_BYTES);

    k_prep<<<(N_FIX * KDIM) / (256 * 16), 256>>>(C);
    k_gemm<<<N_FIX / BM, 256, SMEM_BYTES>>>(A, C, H, papra, flag, (float*)d_out, out_size);
}